// round 8
// baseline (speedup 1.0000x reference)
#include <cuda_runtime.h>
#include <cstdint>

// ----------------------------------------------------------------------------
// B=128, T=32, F=2048, H=1024, L=20, WV=300; TF gate order i,j,f,o; FORGET_BIAS=1
// ----------------------------------------------------------------------------
#define B_   128
#define T_   32
#define F_   2048
#define H_   1024
#define L_   20
#define WV_  300
#define G4H  4096
#define NBLK 128
#define STG_WORDS 6144       // per pipeline stage: A 128x16 (2048) + B 16x256 (4096)
#define SMEM_BIG  (3 * STG_WORDS * 4)

// ---------------- device scratch ----------------
__device__ float g_xg_enc[(size_t)4096 * 4096];   // [t*128+b][4H]
__device__ float g_xg_dec[(size_t)2560 * 4096];   // [l*128+b][4H]
__device__ float g_zp[(size_t)128 * 128 * 256];   // [bid][batch 128][local n 256]
__device__ float g_hbuf[2][B_ * H_];              // double-buffered h (tf32-rounded)
__device__ float g_hs[(size_t)L_ * B_ * H_];      // decoder outputs
__device__ float g_whE[(size_t)H_ * G4H];         // tf32-rounded Wh (encoder)
__device__ float g_whD[(size_t)H_ * G4H];         // tf32-rounded Wh (decoder)
__device__ float g_wx[(size_t)F_ * G4H];          // tf32-rounded Wx (encoder, [k][n])
__device__ float g_frames_tf[(size_t)4096 * F_];  // [m=t*128+b][k] tf32-rounded frames
__device__ unsigned g_flagZ[NBLK * 8];
__device__ unsigned g_flagH[NBLK * 8];

// ---------------- helpers ----------------
__device__ __forceinline__ float f2tf(float x) {
    unsigned u;
    asm("cvt.rna.tf32.f32 %0, %1;" : "=r"(u) : "f"(x));
    return __uint_as_float(u);
}
__device__ __forceinline__ float4 tf4(float4 v) {
    return make_float4(f2tf(v.x), f2tf(v.y), f2tf(v.z), f2tf(v.w));
}
__device__ __forceinline__ void mma8(float* c, const float* a, const float* b) {
    asm volatile(
        "mma.sync.aligned.m16n8k8.row.col.f32.tf32.tf32.f32 "
        "{%0,%1,%2,%3},{%4,%5,%6,%7},{%8,%9},{%0,%1,%2,%3};"
        : "+f"(c[0]), "+f"(c[1]), "+f"(c[2]), "+f"(c[3])
        : "r"(__float_as_uint(a[0])), "r"(__float_as_uint(a[1])),
          "r"(__float_as_uint(a[2])), "r"(__float_as_uint(a[3])),
          "r"(__float_as_uint(b[0])), "r"(__float_as_uint(b[1])));
}
__device__ __forceinline__ float sigf(float x) { return 1.f / (1.f + __expf(-x)); }

__device__ __forceinline__ uint32_t smem_u32(const void* p) {
    return (uint32_t)__cvta_generic_to_shared(p);
}
__device__ __forceinline__ void cpa16(uint32_t dst, const void* src) {
    asm volatile("cp.async.cg.shared.global [%0], [%1], 16;" :: "r"(dst), "l"(src));
}
#define CP_COMMIT() asm volatile("cp.async.commit_group;")
#define CP_WAIT1()  asm volatile("cp.async.wait_group 1;")

// ============================================================================
// Shared tile math for the 128x256 (BK=16) cp.async pipelined GEMM core.
// 512 threads, 16 warps (4 wm x 4 wn), warp tile 32x64, acc[2][8][4].
// A smem: [m][16] with col-swizzle k ^ (((m>>1)&3)<<2) (conflict-free).
// B smem: [k][256] with col-swizzle n ^ ((k&3)<<3)     (conflict-free).
// ============================================================================
struct CoreIds {
    int lane, wid, wm, wn, gid, tig, swzA;
    int ar, akq, a_dst;          // A staging
    int bk, bn, b_dst;           // B staging
};
__device__ __forceinline__ CoreIds core_ids(int tid) {
    CoreIds s;
    s.lane = tid & 31; s.wid = tid >> 5;
    s.wm = s.wid >> 2; s.wn = s.wid & 3;
    s.gid = s.lane >> 2; s.tig = s.lane & 3;
    s.swzA = ((s.gid >> 1) & 3) << 2;
    s.ar = tid >> 2; s.akq = (tid & 3) << 2;
    s.a_dst = s.ar * 16 + (s.akq ^ (((s.ar >> 1) & 3) << 2));
    s.bk = tid >> 5; s.bn = (tid & 31) * 8;
    s.b_dst = 2048 + s.bk * 256 + (s.bn ^ ((s.bk & 3) << 3));
    return s;
}

__device__ __forceinline__ void core_compute(
    const float* __restrict__ a_s, const float* __restrict__ b_s,
    const CoreIds& s, float acc[2][8][4])
{
#pragma unroll
    for (int ks = 0; ks < 16; ks += 8) {
        float af[2][4], bf[8][2];
#pragma unroll
        for (int mf = 0; mf < 2; mf++) {
            const int m0 = s.wm * 32 + mf * 16 + s.gid;
            const int c0 = (ks + s.tig) ^ s.swzA;
            const int c1 = (ks + s.tig + 4) ^ s.swzA;
            af[mf][0] = a_s[m0 * 16 + c0];
            af[mf][1] = a_s[(m0 + 8) * 16 + c0];
            af[mf][2] = a_s[m0 * 16 + c1];
            af[mf][3] = a_s[(m0 + 8) * 16 + c1];
        }
#pragma unroll
        for (int nf = 0; nf < 8; nf++) {
            const int n = (s.wn * 64 + nf * 8 + s.gid) ^ (s.tig << 3);
            bf[nf][0] = b_s[(ks + s.tig) * 256 + n];
            bf[nf][1] = b_s[(ks + s.tig + 4) * 256 + n];
        }
#pragma unroll
        for (int mf = 0; mf < 2; mf++)
#pragma unroll
            for (int nf = 0; nf < 8; nf++) mma8(acc[mf][nf], af[mf], bf[nf]);
    }
}

// ============================================================================
// Encoder XG GEMM: g_xg_enc[m][n] = frames_tf[m][:] . wx[:][n] + bias[n]
// Grid (16 ntiles, 32 mtiles), tile 128x256, K=2048 (128 kt).
// ============================================================================
__global__ void __launch_bounds__(512)
mm0_big(const float* __restrict__ bias)
{
    extern __shared__ float dsm[];
    const int tid = threadIdx.x;
    const CoreIds s = core_ids(tid);
    const uint32_t smb = smem_u32(dsm);
    const int ntile = blockIdx.x, mtile = blockIdx.y;

    const float* arow = g_frames_tf + (size_t)(mtile * 128 + s.ar) * F_;
    const float* bsrc = g_wx + ntile * 256 + s.bn;

    float acc[2][8][4] = {};
    const int NK = F_ / 16;   // 128

    auto issue = [&](int st) {
        const uint32_t sb = smb + (uint32_t)((st % 3) * STG_WORDS) * 4;
        const int kb = st * 16;
        cpa16(sb + s.a_dst * 4, arow + kb + s.akq);
        const float* bp = bsrc + (size_t)(kb + s.bk) * G4H;
        cpa16(sb + s.b_dst * 4, bp);
        cpa16(sb + (s.b_dst + 4) * 4, bp + 4);
    };

    issue(0); CP_COMMIT();
    issue(1); CP_COMMIT();

    for (int kt = 0; kt < NK; ++kt) {
        CP_WAIT1();
        __syncthreads();
        if (kt + 2 < NK) issue(kt + 2);
        CP_COMMIT();
        const float* a_s = dsm + (kt % 3) * STG_WORDS;
        core_compute(a_s, a_s + 2048, s, acc);
    }

#pragma unroll
    for (int mf = 0; mf < 2; mf++)
#pragma unroll
        for (int nf = 0; nf < 8; nf++) {
            const int col = ntile * 256 + s.wn * 64 + nf * 8 + 2 * s.tig;
            const float2 bb = *(const float2*)(bias + col);
#pragma unroll
            for (int r = 0; r < 2; r++) {
                const int row = mtile * 128 + s.wm * 32 + mf * 16 + s.gid + r * 8;
                *(float2*)&g_xg_enc[(size_t)row * G4H + col] =
                    make_float2(acc[mf][nf][2 * r] + bb.x,
                                acc[mf][nf][2 * r + 1] + bb.y);
            }
        }
}

// ============================================================================
// Persistent recurrence: 128 blocks = 16 n-groups x 8 k-splits.
// Block (g, ks): z-partials for 4 gate strips {gate*1024 + g*64 .. +64}
// over k in [ks*128, ks*128+128). Group sync (8 blocks) -> gates for
// b in [ks*16..+16) x hc in [g*64..+64), c in registers -> full barrier.
// ============================================================================
__global__ void __launch_bounds__(512)
lstm_persist()
{
    extern __shared__ float dsm[];
    const int tid = threadIdx.x, bid = blockIdx.x;
    const CoreIds s = core_ids(tid);
    const uint32_t smb = smem_u32(dsm);

    const int g = bid >> 3, ks = bid & 7;
    const int k0 = ks * 128;

    // striped B column mapping: local n -> gate strip
    const int strip = s.bn >> 6;
    const size_t bcol = (size_t)strip * 1024 + g * 64 + (s.bn & 63);

    // gate ids: thread owns 2 elements (gb, ghc..ghc+1)
    const int rb = tid >> 5, rc = (tid & 31) * 2;
    const int gb = ks * 16 + rb;
    const int ghc = g * 64 + rc;
    float2 creg = make_float2(0.f, 0.f);

    for (int t = 0; t < T_ + L_; ++t) {
        const bool dec = (t >= T_);
        const int st = dec ? t - T_ : t;
        const float* wh = dec ? g_whD : g_whE;
        const float* hsrc = g_hbuf[t & 1];
        const float* xg = (dec ? g_xg_dec : g_xg_enc) + (size_t)st * (B_ * G4H);

        float acc[2][8][4] = {};

        auto issue = [&](int si) {
            const uint32_t sb = smb + (uint32_t)((si % 3) * STG_WORDS) * 4;
            const int kb = k0 + si * 16;
            cpa16(sb + s.a_dst * 4, hsrc + (size_t)s.ar * H_ + kb + s.akq);
            const float* bp = wh + (size_t)(kb + s.bk) * G4H + bcol;
            cpa16(sb + s.b_dst * 4, bp);
            cpa16(sb + (s.b_dst + 4) * 4, bp + 4);
        };

        issue(0); CP_COMMIT();
        issue(1); CP_COMMIT();

        for (int kt = 0; kt < 8; ++kt) {
            CP_WAIT1();
            __syncthreads();
            if (kt + 2 < 8) issue(kt + 2);
            CP_COMMIT();
            const float* a_s = dsm + (kt % 3) * STG_WORDS;
            core_compute(a_s, a_s + 2048, s, acc);
        }

        // ---- store z partials: g_zp[bid][row][n] ----
#pragma unroll
        for (int mf = 0; mf < 2; mf++)
#pragma unroll
            for (int nf = 0; nf < 8; nf++) {
                const int col = s.wn * 64 + nf * 8 + 2 * s.tig;
#pragma unroll
                for (int r = 0; r < 2; r++) {
                    const int row = s.wm * 32 + mf * 16 + s.gid + r * 8;
                    *(float2*)&g_zp[((size_t)bid * 128 + row) * 256 + col] =
                        make_float2(acc[mf][nf][2 * r], acc[mf][nf][2 * r + 1]);
                }
            }

        // ---- group sync (8 k-split blocks of this n-group) ----
        __syncthreads();
        __threadfence();
        if (tid == 0) *(volatile unsigned*)&g_flagZ[bid * 8] = (unsigned)(t + 1);
        if (tid < 8) {
            volatile unsigned* f = &g_flagZ[(g * 8 + tid) * 8];
            while (*f < (unsigned)(t + 1)) {}
        }
        __threadfence();
        __syncthreads();

        // ---- gates ----
        {
            float2 z[4];
#pragma unroll
            for (int gt = 0; gt < 4; gt++) {
                float2 v = *(const float2*)(xg + (size_t)gb * G4H + gt * 1024 + ghc);
#pragma unroll
                for (int kp = 0; kp < 8; kp++) {
                    const float2 p = __ldcg((const float2*)(
                        g_zp + ((size_t)(g * 8 + kp) * 128 + gb) * 256 + gt * 64 + rc));
                    v.x += p.x; v.y += p.y;
                }
                z[gt] = v;
            }
            float2 hn;
            {
                const float ig = sigf(z[0].x);
                const float jg = tanhf(z[1].x);
                const float fg = sigf(z[2].x + 1.0f);   // FORGET_BIAS
                const float og = sigf(z[3].x);
                creg.x = creg.x * fg + ig * jg;
                hn.x = tanhf(creg.x) * og;
            }
            {
                const float ig = sigf(z[0].y);
                const float jg = tanhf(z[1].y);
                const float fg = sigf(z[2].y + 1.0f);
                const float og = sigf(z[3].y);
                creg.y = creg.y * fg + ig * jg;
                hn.y = tanhf(creg.y) * og;
            }
            const float2 ho = make_float2(f2tf(hn.x), f2tf(hn.y));
            *(float2*)(g_hbuf[(t + 1) & 1] + (size_t)gb * H_ + ghc) = ho;
            if (dec)
                *(float2*)(g_hs + ((size_t)st * B_ + gb) * H_ + ghc) = ho;
        }

        // ---- full barrier ----
        __syncthreads();
        __threadfence();
        if (tid == 0) *(volatile unsigned*)&g_flagH[bid * 8] = (unsigned)(t + 1);
        if (tid < NBLK) {
            volatile unsigned* f = &g_flagH[tid * 8];
            while (*f < (unsigned)(t + 1)) __nanosleep(64);
        }
        __threadfence();
        __syncthreads();
    }
}

// ============================================================================
// mm_tf32 (SIMT, legacy mma): MODE 1 (dec XG, gather), MODE 2 (projection)
// ============================================================================
#define ASTR 20
#define BSTR 136
struct TIds {
    int lane, wid, wm, wn, gid, tig;
    int ar, ak, bk, bn;
};
__device__ __forceinline__ TIds make_ids(int tid) {
    TIds s;
    s.lane = tid & 31; s.wid = tid >> 5;
    s.wm = s.wid >> 2; s.wn = s.wid & 3;
    s.gid = s.lane >> 2; s.tig = s.lane & 3;
    s.ar = tid >> 2; s.ak = (tid & 3) * 4;
    s.bk = tid >> 5; s.bn = (tid & 31) * 4;
    return s;
}
__device__ __forceinline__ void compute_bk16(
    const float* a_s, const float* b_s, const TIds& s, float acc[2][4][4])
{
#pragma unroll
    for (int ks = 0; ks < 16; ks += 8) {
        float af[2][4], bf[4][2];
#pragma unroll
        for (int mf = 0; mf < 2; mf++) {
            const int m = s.wm * 32 + mf * 16 + s.gid;
            af[mf][0] = a_s[(m)     * ASTR + ks + s.tig];
            af[mf][1] = a_s[(m + 8) * ASTR + ks + s.tig];
            af[mf][2] = a_s[(m)     * ASTR + ks + s.tig + 4];
            af[mf][3] = a_s[(m + 8) * ASTR + ks + s.tig + 4];
        }
#pragma unroll
        for (int nf = 0; nf < 4; nf++) {
            const int n = s.wn * 32 + nf * 8 + s.gid;
            bf[nf][0] = b_s[(ks + s.tig)     * BSTR + n];
            bf[nf][1] = b_s[(ks + s.tig + 4) * BSTR + n];
        }
#pragma unroll
        for (int mf = 0; mf < 2; mf++)
#pragma unroll
            for (int nf = 0; nf < 4; nf++) mma8(acc[mf][nf], af[mf], bf[nf]);
    }
}

template <int MODE>
__global__ void __launch_bounds__(512)
mm_tf32(const float* __restrict__ A, const float* __restrict__ Bm,
        const float* __restrict__ bias, float* __restrict__ Cout,
        const int* __restrict__ caption, int Kv, int ldb)
{
    __shared__ __align__(16) float a_s[2][128 * ASTR];
    __shared__ __align__(16) float b_s[2][16 * BSTR];

    const int tid = threadIdx.x;
    const TIds s = make_ids(tid);
    const int n0 = blockIdx.x * 128;
    const int mtile = blockIdx.y;

    const int m = mtile * 128 + s.ar;
    size_t aoff;
    if constexpr (MODE == 1)
        aoff = (size_t)caption[(m & 127) * L_ + (m >> 7)] * WV_;
    else
        aoff = (size_t)m * H_;
    const float* arow = ((MODE == 2) ? (const float*)g_hs : A) + aoff;

    float acc[2][4][4] = {};
    const int NK = (Kv + 15) / 16;

    auto stage = [&](int it, int buf) {
        const int kb = it * 16;
        {
            const int gk = kb + s.ak;
            float4 v = make_float4(0.f, 0.f, 0.f, 0.f);
            if (MODE != 1 || gk < Kv) v = *(const float4*)(arow + gk);
            *(float4*)&a_s[buf][s.ar * ASTR + s.ak] = tf4(v);
        }
        {
            const int gk = kb + s.bk;
            const int gn = n0 + s.bn;
            float4 v = make_float4(0.f, 0.f, 0.f, 0.f);
            const bool kok = (MODE == 1) ? (gk < Kv) : true;
            const bool nok = (MODE == 2) ? (gn < WV_) : true;
            if (kok && nok) v = *(const float4*)(Bm + (size_t)gk * ldb + gn);
            *(float4*)&b_s[buf][s.bk * BSTR + s.bn] = tf4(v);
        }
    };

    stage(0, 0);
    __syncthreads();
    int buf = 0;
    for (int it = 0; it < NK; ++it) {
        if (it + 1 < NK) stage(it + 1, buf ^ 1);
        compute_bk16(a_s[buf], b_s[buf], s, acc);
        __syncthreads();
        buf ^= 1;
    }

#pragma unroll
    for (int mf = 0; mf < 2; mf++)
#pragma unroll
        for (int nf = 0; nf < 4; nf++) {
            const int col = n0 + s.wn * 32 + nf * 8 + 2 * s.tig;
            const int mrow = mtile * 128 + s.wm * 32 + mf * 16 + s.gid;
#pragma unroll
            for (int r = 0; r < 2; r++) {
                const int row = mrow + r * 8;
                const float v0 = acc[mf][nf][2 * r];
                const float v1 = acc[mf][nf][2 * r + 1];
                if constexpr (MODE == 2) {
                    if (col < WV_) {
                        const size_t co = (size_t)((row & 127) * L_ + (row >> 7)) * WV_;
                        Cout[co + col]     = v0 + bias[col];
                        Cout[co + col + 1] = v1 + bias[col + 1];
                    }
                } else {
                    float* dst = g_xg_dec + (size_t)row * G4H + col;
                    *(float2*)dst = make_float2(v0 + bias[col], v1 + bias[col + 1]);
                }
            }
        }
}

// ---- prep kernels ----
__global__ void __launch_bounds__(512)
conv_wh(const float* __restrict__ encK, const float* __restrict__ decK)
{
    const size_t i4 = ((size_t)blockIdx.x * 512 + threadIdx.x) * 4;
    if (i4 < (size_t)H_ * G4H) {
        *(float4*)&g_whE[i4] = tf4(*(const float4*)(encK + (size_t)F_  * G4H + i4));
        *(float4*)&g_whD[i4] = tf4(*(const float4*)(decK + (size_t)WV_ * G4H + i4));
    }
}

__global__ void __launch_bounds__(512)
conv_wx(const float* __restrict__ encK)
{
    const size_t i4 = ((size_t)blockIdx.x * 512 + threadIdx.x) * 4;
    if (i4 < (size_t)F_ * G4H)
        *(float4*)&g_wx[i4] = tf4(*(const float4*)(encK + i4));
}

__global__ void __launch_bounds__(512)
prep_frames(const float* __restrict__ frames)
{
    const size_t i4 = ((size_t)blockIdx.x * 512 + threadIdx.x) * 4;
    if (i4 < (size_t)4096 * F_) {
        const int m = (int)(i4 / F_), k = (int)(i4 % F_);
        const int b = m & 127, t = m >> 7;
        const float4 v = *(const float4*)(frames + ((size_t)b * T_ + t) * F_ + k);
        *(float4*)&g_frames_tf[i4] = tf4(v);
    }
}

__global__ void init_k()
{
    const int i = blockIdx.x * 256 + threadIdx.x;
    if (i < B_ * H_) g_hbuf[0][i] = 0.f;
    if (i < NBLK * 8) { g_flagZ[i] = 0u; g_flagH[i] = 0u; }
}

// ----------------------------------------------------------------------------
extern "C" void kernel_launch(void* const* d_in, const int* in_sizes, int n_in,
                              void* d_out, int out_size)
{
    const float* frames  = (const float*)d_in[0];
    const int*   caption = (const int*)  d_in[1];
    const float* emb     = (const float*)d_in[2];
    const float* encK    = (const float*)d_in[3];
    const float* encB    = (const float*)d_in[4];
    const float* decK    = (const float*)d_in[5];
    const float* decB    = (const float*)d_in[6];
    const float* projW   = (const float*)d_in[7];
    const float* projB   = (const float*)d_in[8];
    float*       out     = (float*)d_out;

    cudaFuncSetAttribute(mm0_big, cudaFuncAttributeMaxDynamicSharedMemorySize, SMEM_BIG);
    cudaFuncSetAttribute(lstm_persist, cudaFuncAttributeMaxDynamicSharedMemorySize, SMEM_BIG);

    init_k<<<512, 256>>>();
    conv_wh<<<2048, 512>>>(encK, decK);
    conv_wx<<<4096, 512>>>(encK);
    prep_frames<<<4096, 512>>>(frames);

    // encoder input gates: [4096,2048] x [2048,4096] + enc_bias
    mm0_big<<<dim3(16, 32), 512, SMEM_BIG>>>(encB);

    // decoder input gates: gather(emb) [2560,300] x [300,4096] + dec_bias
    mm_tf32<1><<<dim3(32, 20), 512>>>(emb, decK, decB, nullptr, caption, WV_, G4H);

    // full recurrence (32 enc + 20 dec), one persistent kernel
    lstm_persist<<<NBLK, 512, SMEM_BIG>>>();

    // projection: [2560,1024] x [1024,300] + proj_b -> out[b][l][wv]
    mm_tf32<2><<<dim3(3, 20), 512>>>(nullptr, projW, projB, out, nullptr, H_, WV_);
}